// round 10
// baseline (speedup 1.0000x reference)
#include <cuda_runtime.h>

// Chunked-parallel Elman RNN, k-pair-packed f32x2 FMA + 2-way intra-thread ILP.
// All chunks share W: each thread runs TWO independent chunk recurrences from
// the same 60 weight registers, interleaved at compile time so each chain's
// ~150-cycle serial latency (LDS->FMA->tanh->STS) is filled by the other.

#define T_LEN      2000000
#define HDIM       30
#define NPAIR      15            // k-pairs per row
#define NBLOCKS    148           // 1 block / SM
#define NTHREADS   256
#define CPB        32            // chunks per block: 8 warps x 2 SIMD x 2 ILP
#define NCHUNKS    (NBLOCKS * CPB)                    // 4736
#define CHUNK_LEN  ((T_LEN + NCHUNKS - 1) / NCHUNKS)  // 423
#define WARMUP     40
#define HSLOT      32            // floats per h buffer (30 used + 2 pad)
#define CSLOT      (2 * HSLOT)   // ping-pong pair per chunk

typedef unsigned long long u64;

__device__ __forceinline__ u64 fma2(u64 a, u64 b, u64 c) {
    u64 d;
    asm("fma.rn.f32x2 %0, %1, %2, %3;" : "=l"(d) : "l"(a), "l"(b), "l"(c));
    return d;
}
__device__ __forceinline__ u64 add2(u64 a, u64 b) {
    u64 d;
    asm("add.rn.f32x2 %0, %1, %2;" : "=l"(d) : "l"(a), "l"(b));
    return d;
}
__device__ __forceinline__ u64 pack2(float lo, float hi) {
    u64 d;
    asm("mov.b64 %0, {%1, %2};" : "=l"(d) : "f"(lo), "f"(hi));
    return d;
}
__device__ __forceinline__ void unpack2(u64 v, float& lo, float& hi) {
    asm("mov.b64 {%0, %1}, %2;" : "=f"(lo), "=f"(hi) : "l"(v));
}

__device__ __forceinline__ float ftanh(float v) {
    // tanh(v) = 1 - 2/(exp(2v)+1): 2 MUFU + ~4 fma-class ops.
    float e = __expf(2.0f * v);
    return 1.0f - __fdividef(2.0f, e + 1.0f);
}

__global__ void __launch_bounds__(NTHREADS, 1)
rnn_chunked(const float* __restrict__ x,
            const float* __restrict__ W_ih,
            const float* __restrict__ W_hh,
            const float* __restrict__ b_ih,
            const float* __restrict__ b_hh,
            const float* __restrict__ W_fc,
            const float* __restrict__ b_fc,
            float* __restrict__ out)
{
    __shared__ __align__(16) float hbuf[CPB * CSLOT];

    const int tid  = threadIdx.x;
    const int w    = tid >> 5;           // warp 0..7
    const int lane = tid & 31;
    const int g    = lane >> 4;          // SIMD chunk-group within warp (0/1)
    const int j    = lane & 15;          // lane within 16-lane chunk group
    const int r0   = 2 * j;              // rows r0, r0+1 (lane 15 -> padding)

    const int slotA = w * 4 + g * 2;         // smem slot / chunk offset, chain A
    const int slotB = slotA + 1;             // chain B
    const int chunkA = blockIdx.x * CPB + slotA;
    const int chunkB = chunkA + 1;

    // ---- shared register-resident k-pair-packed weights (both chains) ----
    u64 wp0[NPAIR], wp1[NPAIR];
    const int ra = r0, rb = r0 + 1;
    const bool oka = (ra < HDIM), okb = (rb < HDIM);
#pragma unroll
    for (int m = 0; m < NPAIR; m++) {
        wp0[m] = pack2(oka ? W_hh[ra * HDIM + 2 * m] : 0.0f,
                       oka ? W_hh[ra * HDIM + 2 * m + 1] : 0.0f);
        wp1[m] = pack2(okb ? W_hh[rb * HDIM + 2 * m] : 0.0f,
                       okb ? W_hh[rb * HDIM + 2 * m + 1] : 0.0f);
    }
    const float bsum0 = oka ? (b_ih[ra] + b_hh[ra]) : 0.0f;
    const float bsum1 = okb ? (b_ih[rb] + b_hh[rb]) : 0.0f;
    const float wia0  = oka ? W_ih[2 * ra]     : 0.0f;
    const float wia1  = oka ? W_ih[2 * ra + 1] : 0.0f;
    const float wib0  = okb ? W_ih[2 * rb]     : 0.0f;
    const float wib1  = okb ? W_ih[2 * rb + 1] : 0.0f;
    const float wo0   = oka ? W_fc[ra] : 0.0f;
    const float wo1   = okb ? W_fc[rb] : 0.0f;
    const float bfc   = b_fc[0];

    float* hcA = hbuf + slotA * CSLOT;
    float* hcB = hbuf + slotB * CSLOT;
    *(float2*)(hcA + r0)         = make_float2(0.f, 0.f);
    *(float2*)(hcA + HSLOT + r0) = make_float2(0.f, 0.f);
    *(float2*)(hcB + r0)         = make_float2(0.f, 0.f);
    *(float2*)(hcB + HSLOT + r0) = make_float2(0.f, 0.f);
    __syncthreads();

    const int emit0A = chunkA * CHUNK_LEN;
    const int emit0B = chunkB * CHUNK_LEN;
    int t0A = emit0A - WARMUP; if (t0A < 0) t0A = 0;
    int t0B = emit0B - WARMUP; if (t0B < 0) t0B = 0;
    const int emitEndA = (emit0A + CHUNK_LEN < T_LEN) ? (emit0A + CHUNK_LEN) : T_LEN;
    const int emitEndB = (emit0B + CHUNK_LEN < T_LEN) ? (emit0B + CHUNK_LEN) : T_LEN;

    // x prefetch pipelines (depth 2, per chain)
    float2 xaA, xbA, xaB, xbB;
    xaA = (t0A     < T_LEN) ? __ldg((const float2*)x + t0A)     : make_float2(0.f, 0.f);
    xbA = (t0A + 1 < T_LEN) ? __ldg((const float2*)x + t0A + 1) : make_float2(0.f, 0.f);
    xaB = (t0B     < T_LEN) ? __ldg((const float2*)x + t0B)     : make_float2(0.f, 0.f);
    xbB = (t0B + 1 < T_LEN) ? __ldg((const float2*)x + t0B + 1) : make_float2(0.f, 0.f);

    const u64 zz = pack2(0.0f, 0.0f);
    unsigned roff = 0;
    float partA = 0.0f, partB = 0.0f;    // un-reduced y-partials of previous step
    const int ITERS = WARMUP + CHUNK_LEN;         // 463
    for (int i = 0; i < ITERS; i++) {
        const int tA = t0A + i;
        const int tB = t0B + i;

        const float2 xcA = xaA; xaA = xbA;
        const float2 xcB = xaB; xaB = xbB;
        {
            const int tnA = tA + 2, tnB = tB + 2;
            xbA = (tnA < T_LEN) ? __ldg((const float2*)x + tnA) : make_float2(0.f, 0.f);
            xbB = (tnB < T_LEN) ? __ldg((const float2*)x + tnB) : make_float2(0.f, 0.f);
        }

        // input projections (off the h chains)
        const float xpA0 = fmaf(wia1, xcA.y, fmaf(wia0, xcA.x, bsum0));
        const float xpA1 = fmaf(wib1, xcA.y, fmaf(wib0, xcA.x, bsum1));
        const float xpB0 = fmaf(wia1, xcB.y, fmaf(wia0, xcB.x, bsum0));
        const float xpB1 = fmaf(wib1, xcB.y, fmaf(wib0, xcB.x, bsum1));

        const float* hrA = hcA + roff;
        const float* hrB = hcB + roff;
        u64 aA0A = zz, aA0B = zz, aA1A = zz, aA1B = zz;   // chain A accumulators
        u64 aB0A = zz, aB0B = zz, aB1A = zz, aB1B = zz;   // chain B accumulators

        // two independent hh matvecs, interleaved (30 FFMA2 each, 8 LDS each)
#pragma unroll
        for (int m = 0; m < NPAIR - 1; m += 2) {
            const ulonglong2 hvA = *(const ulonglong2*)(hrA + 2 * m);
            const ulonglong2 hvB = *(const ulonglong2*)(hrB + 2 * m);
            aA0A = fma2(wp0[m],     hvA.x, aA0A);
            aB0A = fma2(wp0[m],     hvB.x, aB0A);
            aA1A = fma2(wp1[m],     hvA.x, aA1A);
            aB1A = fma2(wp1[m],     hvB.x, aB1A);
            aA0B = fma2(wp0[m + 1], hvA.y, aA0B);
            aB0B = fma2(wp0[m + 1], hvB.y, aB0B);
            aA1B = fma2(wp1[m + 1], hvA.y, aA1B);
            aB1B = fma2(wp1[m + 1], hvB.y, aB1B);
        }
        {
            const u64 hvA14 = *(const u64*)(hrA + 28);
            const u64 hvB14 = *(const u64*)(hrB + 28);
            aA0A = fma2(wp0[NPAIR - 1], hvA14, aA0A);
            aB0A = fma2(wp0[NPAIR - 1], hvB14, aB0A);
            aA1A = fma2(wp1[NPAIR - 1], hvA14, aA1A);
            aB1A = fma2(wp1[NPAIR - 1], hvB14, aB1A);
        }

        // ---- deferred output reductions for step t-1 (both chains); these
        //      SHFL chains interleave into the matvec/tanh stall windows ----
        {
            float pA = partA, pB = partB;
            pA += __shfl_xor_sync(0xffffffffu, pA, 1);
            pB += __shfl_xor_sync(0xffffffffu, pB, 1);
            pA += __shfl_xor_sync(0xffffffffu, pA, 2);
            pB += __shfl_xor_sync(0xffffffffu, pB, 2);
            pA += __shfl_xor_sync(0xffffffffu, pA, 4);
            pB += __shfl_xor_sync(0xffffffffu, pB, 4);
            pA += __shfl_xor_sync(0xffffffffu, pA, 8);
            pB += __shfl_xor_sync(0xffffffffu, pB, 8);
            if (j == 0) {
                const int tpA = tA - 1, tpB = tB - 1;
                if (tpA >= emit0A && tpA < emitEndA) out[tpA] = pA + bfc;
                if (tpB >= emit0B && tpB < emitEndB) out[tpB] = pB + bfc;
            }
        }

        const u64 sA0 = add2(aA0A, aA0B), sA1 = add2(aA1A, aA1B);
        const u64 sB0 = add2(aB0A, aB0B), sB1 = add2(aB1A, aB1B);

        float eA0, oA0, eA1, oA1, eB0, oB0, eB1, oB1;
        unpack2(sA0, eA0, oA0); unpack2(sA1, eA1, oA1);
        unpack2(sB0, eB0, oB0); unpack2(sB1, eB1, oB1);
        const float hnA0 = ftanh(xpA0 + (eA0 + oA0));
        const float hnB0 = ftanh(xpB0 + (eB0 + oB0));
        const float hnA1 = ftanh(xpA1 + (eA1 + oA1));
        const float hnB1 = ftanh(xpB1 + (eB1 + oB1));

        // publish both h vectors; one syncwarp covers both chains
        *(float2*)(hcA + (roff ^ HSLOT) + r0) = make_float2(hnA0, hnA1);
        *(float2*)(hcB + (roff ^ HSLOT) + r0) = make_float2(hnB0, hnB1);
        roff ^= HSLOT;
        __syncwarp();

        partA = fmaf(wo0, hnA0, wo1 * hnA1);
        partB = fmaf(wo0, hnB0, wo1 * hnB1);
    }

    // ---- epilogue: reduce + emit final step for both chains ----
    {
        float pA = partA, pB = partB;
        pA += __shfl_xor_sync(0xffffffffu, pA, 1);
        pB += __shfl_xor_sync(0xffffffffu, pB, 1);
        pA += __shfl_xor_sync(0xffffffffu, pA, 2);
        pB += __shfl_xor_sync(0xffffffffu, pB, 2);
        pA += __shfl_xor_sync(0xffffffffu, pA, 4);
        pB += __shfl_xor_sync(0xffffffffu, pB, 4);
        pA += __shfl_xor_sync(0xffffffffu, pA, 8);
        pB += __shfl_xor_sync(0xffffffffu, pB, 8);
        if (j == 0) {
            const int tlA = t0A + ITERS - 1, tlB = t0B + ITERS - 1;
            if (tlA >= emit0A && tlA < emitEndA) out[tlA] = pA + bfc;
            if (tlB >= emit0B && tlB < emitEndB) out[tlB] = pB + bfc;
        }
    }
}

extern "C" void kernel_launch(void* const* d_in, const int* in_sizes, int n_in,
                              void* d_out, int out_size) {
    const float* x    = (const float*)d_in[0];
    const float* W_ih = (const float*)d_in[1];
    const float* W_hh = (const float*)d_in[2];
    const float* b_ih = (const float*)d_in[3];
    const float* b_hh = (const float*)d_in[4];
    const float* W_fc = (const float*)d_in[5];
    const float* b_fc = (const float*)d_in[6];
    float* out = (float*)d_out;

    rnn_chunked<<<NBLOCKS, NTHREADS>>>(x, W_ih, W_hh, b_ih, b_hh, W_fc, b_fc, out);
}